// round 2
// baseline (speedup 1.0000x reference)
#include <cuda_runtime.h>

#define Bsz 4
#define Cc  128
#define Hh  64
#define Ww  64
#define Kk  7
#define NHh 8
#define DHh 16
#define PADk 3
#define HW  (Hh*Ww)        // 4096
#define CHW (Cc*HW)        // 524288

typedef unsigned long long ull;

// scratch for projections (allocation-free rule: device globals)
__device__ float g_q[Bsz*CHW];
__device__ float g_k[Bsz*CHW];
__device__ float g_v[Bsz*CHW];

// ---------------- packed f32x2 helpers (sm_103a) ----------------
__device__ __forceinline__ ull fma2(ull a, ull b, ull c) {
    ull d;
    asm("fma.rn.f32x2 %0, %1, %2, %3;" : "=l"(d) : "l"(a), "l"(b), "l"(c));
    return d;
}
__device__ __forceinline__ ull pack2(float lo, float hi) {
    ull d;
    asm("mov.b64 %0, {%1, %2};" : "=l"(d) : "f"(lo), "f"(hi));
    return d;
}
__device__ __forceinline__ float2 unpack2(ull v) {
    float2 r;
    asm("mov.b64 {%0, %1}, %2;" : "=f"(r.x), "=f"(r.y) : "l"(v));
    return r;
}

// ---------------------------------------------------------------------------
// Kernel 1: fused QKV 1x1-conv GEMM with packed f32x2 FMA.
// out[m,n] = sum_c W[m,c]*x[c,n] + bias[m];  M=128, N=16384, Kdim=128.
// blockIdx.y selects projection. BM=BN=128, BK=16, 256 thr, 8x8 per thread
// (accumulated as 8x4 f32x2 pairs over n).
// ---------------------------------------------------------------------------
__global__ __launch_bounds__(256) void qkv_gemm(
    const float* __restrict__ x,
    const float* __restrict__ wq, const float* __restrict__ bq,
    const float* __restrict__ wk, const float* __restrict__ bk,
    const float* __restrict__ wv, const float* __restrict__ bv)
{
    __shared__ ull   Ws2[16][132];   // [kk][m] duplicated (w,w) pairs, padded
    __shared__ float Bs[16][128];    // [kk][n]

    const float* W; const float* bias; float* out;
    if (blockIdx.y == 0)      { W = wq; bias = bq; out = g_q; }
    else if (blockIdx.y == 1) { W = wk; bias = bk; out = g_k; }
    else                      { W = wv; bias = bv; out = g_v; }

    const int tid = threadIdx.x;
    const int tx = tid & 15, ty = tid >> 4;
    const int n0 = blockIdx.x * 128;
    const int b  = n0 >> 12;
    const int hw0 = n0 & 4095;
    const float* xb = x + b * CHW + hw0;

    ull acc2[8][4];
#pragma unroll
    for (int i = 0; i < 8; i++)
#pragma unroll
        for (int j = 0; j < 4; j++) acc2[i][j] = 0ull;

    for (int c0 = 0; c0 < 128; c0 += 16) {
        // W tile: duplicate each value into both lanes
#pragma unroll
        for (int t = tid; t < 2048; t += 256) {
            int m = t >> 4, cc = t & 15;
            float wv_ = W[m * 128 + c0 + cc];
            Ws2[cc][m] = pack2(wv_, wv_);
        }
        // X tile: coalesced along n
#pragma unroll
        for (int t = tid; t < 2048; t += 256) {
            int cc = t >> 7, n = t & 127;
            Bs[cc][n] = xb[(c0 + cc) * HW + n];
        }
        __syncthreads();
#pragma unroll
        for (int kk = 0; kk < 16; kk++) {
            ull a2[8];
            {
                ulonglong2 a01 = *(const ulonglong2*)&Ws2[kk][ty * 4];
                ulonglong2 a23 = *(const ulonglong2*)&Ws2[kk][ty * 4 + 2];
                ulonglong2 a45 = *(const ulonglong2*)&Ws2[kk][64 + ty * 4];
                ulonglong2 a67 = *(const ulonglong2*)&Ws2[kk][64 + ty * 4 + 2];
                a2[0] = a01.x; a2[1] = a01.y; a2[2] = a23.x; a2[3] = a23.y;
                a2[4] = a45.x; a2[5] = a45.y; a2[6] = a67.x; a2[7] = a67.y;
            }
            ulonglong2 bA = *(const ulonglong2*)&Bs[kk][tx * 4];
            ulonglong2 bB = *(const ulonglong2*)&Bs[kk][64 + tx * 4];
#pragma unroll
            for (int i = 0; i < 8; i++) {
                acc2[i][0] = fma2(a2[i], bA.x, acc2[i][0]);
                acc2[i][1] = fma2(a2[i], bA.y, acc2[i][1]);
                acc2[i][2] = fma2(a2[i], bB.x, acc2[i][2]);
                acc2[i][3] = fma2(a2[i], bB.y, acc2[i][3]);
            }
        }
        __syncthreads();
    }

    float* outp = out + b * CHW + hw0;
#pragma unroll
    for (int i = 0; i < 8; i++) {
        int m = (i < 4) ? (ty * 4 + i) : (64 + ty * 4 + (i - 4));
        float bi = bias[m];
        float2 v0 = unpack2(acc2[i][0]);
        float2 v1 = unpack2(acc2[i][1]);
        float2 v2 = unpack2(acc2[i][2]);
        float2 v3 = unpack2(acc2[i][3]);
        float4 lo = make_float4(v0.x + bi, v0.y + bi, v1.x + bi, v1.y + bi);
        float4 hi = make_float4(v2.x + bi, v2.y + bi, v3.x + bi, v3.y + bi);
        *(float4*)(outp + m * HW + tx * 4)      = lo;
        *(float4*)(outp + m * HW + 64 + tx * 4) = hi;
    }
}

// ---------------------------------------------------------------------------
// Kernel 2: local attention, 2 adjacent pixels per thread, single-pass
// softmax WITHOUT max subtraction (logits are bounded ~N(0,4) << 88).
//
// Block = 8x32 pixel tile for one (b, head); 128 threads (16x8), thread
// (tx,ty) owns pixels (h0+ty, w0+2tx) and (h0+ty, w0+2tx+1).
//
// smem layout: interleaved K/V pair-blocks.
//   row r (14 rows), column-pair p (19 pairs of halo columns), block of 68
//   words: [K(c even) d0..15 | K(c odd) d0..15 | V(c even) | V(c odd) | pad4]
//   word offset = r*1292 + p*68 + (c&1)*16 (+32 for V) + d
//   Per (i,c) a warp's 8-lane phase hits banks 4*tx (mod 32) -> conflict-free
//   LDS.128, 16B-aligned (68 words = 272B = 17*16).
// ---------------------------------------------------------------------------
#define RSTRIDE 1292           // 19 * 68
#define SM_WORDS (14 * RSTRIDE) // 18088 words = 72352 B

__global__ __launch_bounds__(128) void attn_kernel(
    const float* __restrict__ bk, const float* __restrict__ bv,
    const float* __restrict__ pos_h, const float* __restrict__ pos_w,
    float* __restrict__ outp)
{
    extern __shared__ float sm[];

    const int tr = blockIdx.x >> 1, tc = blockIdx.x & 1;
    const int h0 = tr * 8, w0 = tc * 32;
    const int nh = blockIdx.y, b = blockIdx.z;
    const int tx = threadIdx.x;   // 0..15
    const int ty = threadIdx.y;   // 0..7
    const int tid = ty * 16 + tx;
    const int cbase = nh * DHh;

    const float* kb = g_k + (size_t)(b * Cc + cbase) * HW;
    const float* vb = g_v + (size_t)(b * Cc + cbase) * HW;

    // ---- fill halo (14 x 38 x 16 for K and V) ----
    for (int idx = tid; idx < 14 * 38 * 16; idx += 128) {
        int d  = idx / (14 * 38);
        int rc = idx - d * (14 * 38);
        int r  = rc / 38, c = rc - r * 38;
        int gh = h0 - PADk + r, gw = w0 - PADk + c;
        float kvv, vvv;
        if ((unsigned)gh < (unsigned)Hh && (unsigned)gw < (unsigned)Ww) {
            int g = d * HW + gh * Ww + gw;
            kvv = kb[g]; vvv = vb[g];
        } else {
            kvv = bk[cbase + d]; vvv = bv[cbase + d];
        }
        int off = r * RSTRIDE + (c >> 1) * 68 + (c & 1) * 16 + d;
        sm[off]      = kvv;
        sm[off + 32] = vvv;
    }
    __syncthreads();

    // ---- load q for both pixels, packed over d-pairs ----
    const int h = h0 + ty, w = w0 + 2 * tx;
    const float* qp = g_q + ((size_t)(b * Cc + cbase) * Hh + h) * Ww + w;
    ull q0p[8], q1p[8];
#pragma unroll
    for (int t = 0; t < 8; t++) {
        float2 qa = *(const float2*)(qp + (2 * t) * HW);
        float2 qb = *(const float2*)(qp + (2 * t + 1) * HW);
        q0p[t] = pack2(qa.x, qb.x);
        q1p[t] = pack2(qa.y, qb.y);
    }

    float ph[7], pw[7];
#pragma unroll
    for (int i = 0; i < 7; i++) {
        ph[i] = pos_h[nh * 7 + i];
        pw[i] = pos_w[nh * 7 + i];
    }

    ull acc0[8], acc1[8];
#pragma unroll
    for (int t = 0; t < 8; t++) { acc0[t] = 0ull; acc1[t] = 0ull; }
    float sum0 = 0.f, sum1 = 0.f;

    for (int i = 0; i < 7; i++) {
        const float* rowp = sm + (ty + i) * RSTRIDE;
        const float phi = ph[i];
#pragma unroll
        for (int c = 0; c < 8; c++) {
            const float* p = rowp + (tx + (c >> 1)) * 68 + (c & 1) * 16;
            ulonglong2 kA = ((const ulonglong2*)p)[0];
            ulonglong2 kB = ((const ulonglong2*)p)[1];
            ulonglong2 kC = ((const ulonglong2*)p)[2];
            ulonglong2 kD = ((const ulonglong2*)p)[3];

            float w0e = 0.f, w1e = 0.f;
            if (c < 7) {   // pixel0 neighbor j = c
                ull s = fma2(q0p[0], kA.x, 0ull);
                s = fma2(q0p[1], kA.y, s);
                s = fma2(q0p[2], kB.x, s);
                s = fma2(q0p[3], kB.y, s);
                s = fma2(q0p[4], kC.x, s);
                s = fma2(q0p[5], kC.y, s);
                s = fma2(q0p[6], kD.x, s);
                s = fma2(q0p[7], kD.y, s);
                float2 f = unpack2(s);
                w0e = __expf(f.x + f.y + phi + pw[c]);
                sum0 += w0e;
            }
            if (c >= 1) {  // pixel1 neighbor j = c-1
                ull s = fma2(q1p[0], kA.x, 0ull);
                s = fma2(q1p[1], kA.y, s);
                s = fma2(q1p[2], kB.x, s);
                s = fma2(q1p[3], kB.y, s);
                s = fma2(q1p[4], kC.x, s);
                s = fma2(q1p[5], kC.y, s);
                s = fma2(q1p[6], kD.x, s);
                s = fma2(q1p[7], kD.y, s);
                float2 f = unpack2(s);
                w1e = __expf(f.x + f.y + phi + pw[c - 1]);
                sum1 += w1e;
            }

            const float* pv = p + 32;
            ulonglong2 vA = ((const ulonglong2*)pv)[0];
            ulonglong2 vB = ((const ulonglong2*)pv)[1];
            ulonglong2 vC = ((const ulonglong2*)pv)[2];
            ulonglong2 vD = ((const ulonglong2*)pv)[3];

            if (c < 7) {
                ull wp = pack2(w0e, w0e);
                acc0[0] = fma2(wp, vA.x, acc0[0]);
                acc0[1] = fma2(wp, vA.y, acc0[1]);
                acc0[2] = fma2(wp, vB.x, acc0[2]);
                acc0[3] = fma2(wp, vB.y, acc0[3]);
                acc0[4] = fma2(wp, vC.x, acc0[4]);
                acc0[5] = fma2(wp, vC.y, acc0[5]);
                acc0[6] = fma2(wp, vD.x, acc0[6]);
                acc0[7] = fma2(wp, vD.y, acc0[7]);
            }
            if (c >= 1) {
                ull wp = pack2(w1e, w1e);
                acc1[0] = fma2(wp, vA.x, acc1[0]);
                acc1[1] = fma2(wp, vA.y, acc1[1]);
                acc1[2] = fma2(wp, vB.x, acc1[2]);
                acc1[3] = fma2(wp, vB.y, acc1[3]);
                acc1[4] = fma2(wp, vC.x, acc1[4]);
                acc1[5] = fma2(wp, vC.y, acc1[5]);
                acc1[6] = fma2(wp, vD.x, acc1[6]);
                acc1[7] = fma2(wp, vD.y, acc1[7]);
            }
        }
    }

    const float inv0 = __fdividef(1.f, sum0);
    const float inv1 = __fdividef(1.f, sum1);

    float* op = outp + ((size_t)(b * Cc + cbase) * Hh + h) * Ww + w;
#pragma unroll
    for (int t = 0; t < 8; t++) {
        float2 a0 = unpack2(acc0[t]);   // pixel0, d = 2t, 2t+1
        float2 a1 = unpack2(acc1[t]);   // pixel1
        float2 olo = make_float2(a0.x * inv0, a1.x * inv1);  // d = 2t
        float2 ohi = make_float2(a0.y * inv0, a1.y * inv1);  // d = 2t+1
        *(float2*)(op + (2 * t) * HW)     = olo;
        *(float2*)(op + (2 * t + 1) * HW) = ohi;
    }
}

// ---------------------------------------------------------------------------
extern "C" void kernel_launch(void* const* d_in, const int* in_sizes, int n_in,
                              void* d_out, int out_size) {
    const float* x  = (const float*)d_in[0];
    const float* wq = (const float*)d_in[1];
    const float* bq = (const float*)d_in[2];
    const float* wk = (const float*)d_in[3];
    const float* bk = (const float*)d_in[4];
    const float* wv = (const float*)d_in[5];
    const float* bv = (const float*)d_in[6];
    const float* ph = (const float*)d_in[7];
    const float* pw = (const float*)d_in[8];
    float* out = (float*)d_out;

    const size_t smem_bytes = SM_WORDS * sizeof(float);  // 72352
    cudaFuncSetAttribute((const void*)attn_kernel,
                         cudaFuncAttributeMaxDynamicSharedMemorySize,
                         (int)smem_bytes);

    qkv_gemm<<<dim3(128, 3), 256>>>(x, wq, bq, wk, bk, wv, bv);
    attn_kernel<<<dim3(16, NHh, Bsz), dim3(16, 8), smem_bytes>>>(bk, bv, ph, pw, out);
}

// round 3
// speedup vs baseline: 1.0242x; 1.0242x over previous
#include <cuda_runtime.h>

#define Bsz 4
#define Cc  128
#define Hh  64
#define Ww  64
#define Kk  7
#define NHh 8
#define DHh 16
#define PADk 3
#define HW  (Hh*Ww)        // 4096
#define CHW (Cc*HW)        // 524288

typedef unsigned long long ull;

// scratch for projections (allocation-free rule: device globals)
__device__ float g_q[Bsz*CHW];
__device__ float g_k[Bsz*CHW];
__device__ float g_v[Bsz*CHW];

// ---------------- packed f32x2 helpers (sm_103a) ----------------
__device__ __forceinline__ ull fma2(ull a, ull b, ull c) {
    ull d;
    asm("fma.rn.f32x2 %0, %1, %2, %3;" : "=l"(d) : "l"(a), "l"(b), "l"(c));
    return d;
}
__device__ __forceinline__ ull add2(ull a, ull b) {
    ull d;
    asm("add.rn.f32x2 %0, %1, %2;" : "=l"(d) : "l"(a), "l"(b));
    return d;
}
__device__ __forceinline__ ull pack2(float lo, float hi) {
    ull d;
    asm("mov.b64 %0, {%1, %2};" : "=l"(d) : "f"(lo), "f"(hi));
    return d;
}
__device__ __forceinline__ float2 unpack2(ull v) {
    float2 r;
    asm("mov.b64 {%0, %1}, %2;" : "=f"(r.x), "=f"(r.y) : "l"(v));
    return r;
}

// ---------------------------------------------------------------------------
// Kernel 1: fused QKV 1x1-conv GEMM, f32x2 FMA + register-prefetch pipeline.
// out[m,n] = sum_c W[m,c]*x[c,n] + bias[m];  M=128, N=16384, Kdim=128.
// blockIdx.y selects projection. BM=BN=128, BK=16, 256 thr, 8x8 per thread.
// ---------------------------------------------------------------------------
__global__ __launch_bounds__(256) void qkv_gemm(
    const float* __restrict__ x,
    const float* __restrict__ wq, const float* __restrict__ bq,
    const float* __restrict__ wk, const float* __restrict__ bk,
    const float* __restrict__ wv, const float* __restrict__ bv)
{
    __shared__ ull   Ws2[16][132];   // [kk][m] duplicated (w,w) pairs, padded
    __shared__ float Bs[16][128];    // [kk][n]

    const float* W; const float* bias; float* out;
    if (blockIdx.y == 0)      { W = wq; bias = bq; out = g_q; }
    else if (blockIdx.y == 1) { W = wk; bias = bk; out = g_k; }
    else                      { W = wv; bias = bv; out = g_v; }

    const int tid = threadIdx.x;
    const int tx = tid & 15, ty = tid >> 4;
    const int n0 = blockIdx.x * 128;
    const int b  = n0 >> 12;
    const int hw0 = n0 & 4095;
    const float* xb = x + b * CHW + hw0;

    // register staging for the prefetch pipeline
    float wst[8], xst[8];
#pragma unroll
    for (int k = 0; k < 8; k++) {
        int t = tid + k * 256;
        wst[k] = W[(t >> 4) * 128 + (t & 15)];
        xst[k] = xb[(t >> 7) * HW + (t & 127)];
    }

    ull acc2[8][4];
#pragma unroll
    for (int i = 0; i < 8; i++)
#pragma unroll
        for (int j = 0; j < 4; j++) acc2[i][j] = 0ull;

    for (int c0 = 0; c0 < 128; c0 += 16) {
        // commit staged tile to smem
#pragma unroll
        for (int k = 0; k < 8; k++) {
            int t = tid + k * 256;
            Ws2[t & 15][t >> 4] = pack2(wst[k], wst[k]);
            Bs[t >> 7][t & 127] = xst[k];
        }
        __syncthreads();

        // prefetch next tile into registers (overlaps with compute below)
        if (c0 < 112) {
            int c1 = c0 + 16;
#pragma unroll
            for (int k = 0; k < 8; k++) {
                int t = tid + k * 256;
                wst[k] = W[(t >> 4) * 128 + c1 + (t & 15)];
                xst[k] = xb[(c1 + (t >> 7)) * HW + (t & 127)];
            }
        }

#pragma unroll
        for (int kk = 0; kk < 16; kk++) {
            ull a2[8];
            {
                ulonglong2 a01 = *(const ulonglong2*)&Ws2[kk][ty * 4];
                ulonglong2 a23 = *(const ulonglong2*)&Ws2[kk][ty * 4 + 2];
                ulonglong2 a45 = *(const ulonglong2*)&Ws2[kk][64 + ty * 4];
                ulonglong2 a67 = *(const ulonglong2*)&Ws2[kk][64 + ty * 4 + 2];
                a2[0] = a01.x; a2[1] = a01.y; a2[2] = a23.x; a2[3] = a23.y;
                a2[4] = a45.x; a2[5] = a45.y; a2[6] = a67.x; a2[7] = a67.y;
            }
            ulonglong2 bA = *(const ulonglong2*)&Bs[kk][tx * 4];
            ulonglong2 bB = *(const ulonglong2*)&Bs[kk][64 + tx * 4];
#pragma unroll
            for (int i = 0; i < 8; i++) {
                acc2[i][0] = fma2(a2[i], bA.x, acc2[i][0]);
                acc2[i][1] = fma2(a2[i], bA.y, acc2[i][1]);
                acc2[i][2] = fma2(a2[i], bB.x, acc2[i][2]);
                acc2[i][3] = fma2(a2[i], bB.y, acc2[i][3]);
            }
        }
        __syncthreads();
    }

    float* outp = out + b * CHW + hw0;
#pragma unroll
    for (int i = 0; i < 8; i++) {
        int m = (i < 4) ? (ty * 4 + i) : (64 + ty * 4 + (i - 4));
        float bi = bias[m];
        float2 v0 = unpack2(acc2[i][0]);
        float2 v1 = unpack2(acc2[i][1]);
        float2 v2 = unpack2(acc2[i][2]);
        float2 v3 = unpack2(acc2[i][3]);
        float4 lo = make_float4(v0.x + bi, v0.y + bi, v1.x + bi, v1.y + bi);
        float4 hi = make_float4(v2.x + bi, v2.y + bi, v3.x + bi, v3.y + bi);
        *(float4*)(outp + m * HW + tx * 4)      = lo;
        *(float4*)(outp + m * HW + 64 + tx * 4) = hi;
    }
}

// ---------------------------------------------------------------------------
// Kernel 2: local attention, 2 adjacent pixels per thread, single-pass
// softmax WITHOUT max subtraction (logits bounded, << 88).
//
// Block = 8x32 pixel tile for one (b, head); 128 threads (16x8); thread
// (tx,ty) owns pixels (h0+ty, w0+2tx) and (h0+ty, w0+2tx+1).
//
// smem layout (proven conflict-free in R2): interleaved K/V pair-blocks.
//   word offset = r*1292 + p*68 + (c&1)*16 (+32 for V) + d
//
// R3 changes vs R2: __launch_bounds__(128,3) lifts the 128-reg cap (no
// spills; smem already limits to 3 blocks/SM), pos tables in smem (-14
// regs), dot chains split 2-way.
// ---------------------------------------------------------------------------
#define RSTRIDE 1292            // 19 * 68
#define SM_WORDS (14 * RSTRIDE) // 18088 words = 72352 B

__global__ __launch_bounds__(128, 3) void attn_kernel(
    const float* __restrict__ bk, const float* __restrict__ bv,
    const float* __restrict__ pos_h, const float* __restrict__ pos_w,
    float* __restrict__ outp)
{
    extern __shared__ float sm[];
    __shared__ float spos[16];   // [0..6]=pos_h row, [7..13]=pos_w row

    const int tr = blockIdx.x >> 1, tc = blockIdx.x & 1;
    const int h0 = tr * 8, w0 = tc * 32;
    const int nh = blockIdx.y, b = blockIdx.z;
    const int tx = threadIdx.x;   // 0..15
    const int ty = threadIdx.y;   // 0..7
    const int tid = ty * 16 + tx;
    const int cbase = nh * DHh;

    const float* kb = g_k + (size_t)(b * Cc + cbase) * HW;
    const float* vb = g_v + (size_t)(b * Cc + cbase) * HW;

    if (tid < 7)               spos[tid] = pos_h[nh * 7 + tid];
    else if (tid < 14)         spos[tid] = pos_w[nh * 7 + tid - 7];

    // ---- fill halo (14 x 38 x 16 for K and V) ----
    for (int idx = tid; idx < 14 * 38 * 16; idx += 128) {
        int d  = idx / (14 * 38);
        int rc = idx - d * (14 * 38);
        int r  = rc / 38, c = rc - r * 38;
        int gh = h0 - PADk + r, gw = w0 - PADk + c;
        float kvv, vvv;
        if ((unsigned)gh < (unsigned)Hh && (unsigned)gw < (unsigned)Ww) {
            int g = d * HW + gh * Ww + gw;
            kvv = kb[g]; vvv = vb[g];
        } else {
            kvv = bk[cbase + d]; vvv = bv[cbase + d];
        }
        int off = r * RSTRIDE + (c >> 1) * 68 + (c & 1) * 16 + d;
        sm[off]      = kvv;
        sm[off + 32] = vvv;
    }
    __syncthreads();

    // ---- load q for both pixels, packed over d-pairs ----
    const int h = h0 + ty, w = w0 + 2 * tx;
    const float* qp = g_q + ((size_t)(b * Cc + cbase) * Hh + h) * Ww + w;
    ull q0p[8], q1p[8];
#pragma unroll
    for (int t = 0; t < 8; t++) {
        float2 qa = *(const float2*)(qp + (2 * t) * HW);
        float2 qb = *(const float2*)(qp + (2 * t + 1) * HW);
        q0p[t] = pack2(qa.x, qb.x);
        q1p[t] = pack2(qa.y, qb.y);
    }

    ull acc0[8], acc1[8];
#pragma unroll
    for (int t = 0; t < 8; t++) { acc0[t] = 0ull; acc1[t] = 0ull; }
    float sum0 = 0.f, sum1 = 0.f;

#pragma unroll 1
    for (int i = 0; i < 7; i++) {
        const float* rowp = sm + (ty + i) * RSTRIDE;
        const float phi = spos[i];
#pragma unroll
        for (int c = 0; c < 8; c++) {
            const float* p = rowp + (tx + (c >> 1)) * 68 + (c & 1) * 16;
            ulonglong2 kA = ((const ulonglong2*)p)[0];
            ulonglong2 kB = ((const ulonglong2*)p)[1];
            ulonglong2 kC = ((const ulonglong2*)p)[2];
            ulonglong2 kD = ((const ulonglong2*)p)[3];

            float w0e = 0.f, w1e = 0.f;
            if (c < 7) {   // pixel0 neighbor j = c
                ull sA = fma2(q0p[0], kA.x, 0ull);
                ull sB = fma2(q0p[1], kA.y, 0ull);
                sA = fma2(q0p[2], kB.x, sA);
                sB = fma2(q0p[3], kB.y, sB);
                sA = fma2(q0p[4], kC.x, sA);
                sB = fma2(q0p[5], kC.y, sB);
                sA = fma2(q0p[6], kD.x, sA);
                sB = fma2(q0p[7], kD.y, sB);
                float2 f = unpack2(add2(sA, sB));
                w0e = __expf(f.x + f.y + phi + spos[7 + c]);
                sum0 += w0e;
            }
            if (c >= 1) {  // pixel1 neighbor j = c-1
                ull sA = fma2(q1p[0], kA.x, 0ull);
                ull sB = fma2(q1p[1], kA.y, 0ull);
                sA = fma2(q1p[2], kB.x, sA);
                sB = fma2(q1p[3], kB.y, sB);
                sA = fma2(q1p[4], kC.x, sA);
                sB = fma2(q1p[5], kC.y, sB);
                sA = fma2(q1p[6], kD.x, sA);
                sB = fma2(q1p[7], kD.y, sB);
                float2 f = unpack2(add2(sA, sB));
                w1e = __expf(f.x + f.y + phi + spos[7 + c - 1]);
                sum1 += w1e;
            }

            const float* pv = p + 32;
            ulonglong2 vA = ((const ulonglong2*)pv)[0];
            ulonglong2 vB = ((const ulonglong2*)pv)[1];
            ulonglong2 vC = ((const ulonglong2*)pv)[2];
            ulonglong2 vD = ((const ulonglong2*)pv)[3];

            if (c < 7) {
                ull wp = pack2(w0e, w0e);
                acc0[0] = fma2(wp, vA.x, acc0[0]);
                acc0[1] = fma2(wp, vA.y, acc0[1]);
                acc0[2] = fma2(wp, vB.x, acc0[2]);
                acc0[3] = fma2(wp, vB.y, acc0[3]);
                acc0[4] = fma2(wp, vC.x, acc0[4]);
                acc0[5] = fma2(wp, vC.y, acc0[5]);
                acc0[6] = fma2(wp, vD.x, acc0[6]);
                acc0[7] = fma2(wp, vD.y, acc0[7]);
            }
            if (c >= 1) {
                ull wp = pack2(w1e, w1e);
                acc1[0] = fma2(wp, vA.x, acc1[0]);
                acc1[1] = fma2(wp, vA.y, acc1[1]);
                acc1[2] = fma2(wp, vB.x, acc1[2]);
                acc1[3] = fma2(wp, vB.y, acc1[3]);
                acc1[4] = fma2(wp, vC.x, acc1[4]);
                acc1[5] = fma2(wp, vC.y, acc1[5]);
                acc1[6] = fma2(wp, vD.x, acc1[6]);
                acc1[7] = fma2(wp, vD.y, acc1[7]);
            }
        }
    }

    const float inv0 = __fdividef(1.f, sum0);
    const float inv1 = __fdividef(1.f, sum1);

    float* op = outp + ((size_t)(b * Cc + cbase) * Hh + h) * Ww + w;
#pragma unroll
    for (int t = 0; t < 8; t++) {
        float2 a0 = unpack2(acc0[t]);   // pixel0, d = 2t, 2t+1
        float2 a1 = unpack2(acc1[t]);   // pixel1
        float2 olo = make_float2(a0.x * inv0, a1.x * inv1);  // d = 2t
        float2 ohi = make_float2(a0.y * inv0, a1.y * inv1);  // d = 2t+1
        *(float2*)(op + (2 * t) * HW)     = olo;
        *(float2*)(op + (2 * t + 1) * HW) = ohi;
    }
}

// ---------------------------------------------------------------------------
extern "C" void kernel_launch(void* const* d_in, const int* in_sizes, int n_in,
                              void* d_out, int out_size) {
    const float* x  = (const float*)d_in[0];
    const float* wq = (const float*)d_in[1];
    const float* bq = (const float*)d_in[2];
    const float* wk = (const float*)d_in[3];
    const float* bk = (const float*)d_in[4];
    const float* wv = (const float*)d_in[5];
    const float* bv = (const float*)d_in[6];
    const float* ph = (const float*)d_in[7];
    const float* pw = (const float*)d_in[8];
    float* out = (float*)d_out;

    const size_t smem_bytes = SM_WORDS * sizeof(float);  // 72352
    cudaFuncSetAttribute((const void*)attn_kernel,
                         cudaFuncAttributeMaxDynamicSharedMemorySize,
                         (int)smem_bytes);

    qkv_gemm<<<dim3(128, 3), 256>>>(x, wq, bq, wk, bk, wv, bv);
    attn_kernel<<<dim3(16, NHh, Bsz), dim3(16, 8), smem_bytes>>>(bk, bv, ph, pw, out);
}

// round 4
// speedup vs baseline: 1.1062x; 1.0800x over previous
#include <cuda_runtime.h>

#define Bsz 4
#define Cc  128
#define Hh  64
#define Ww  64
#define Kk  7
#define NHh 8
#define DHh 16
#define PADk 3
#define HW  (Hh*Ww)        // 4096
#define CHW (Cc*HW)        // 524288

typedef unsigned long long ull;

// scratch for projections, CHANNEL-LAST layout [b][hw][c] (c = head*16+d)
__device__ float g_q[Bsz*CHW];
__device__ float g_k[Bsz*CHW];
__device__ float g_v[Bsz*CHW];

// ---------------- packed f32x2 helpers (sm_103a) ----------------
__device__ __forceinline__ ull fma2(ull a, ull b, ull c) {
    ull d;
    asm("fma.rn.f32x2 %0, %1, %2, %3;" : "=l"(d) : "l"(a), "l"(b), "l"(c));
    return d;
}
__device__ __forceinline__ ull add2(ull a, ull b) {
    ull d;
    asm("add.rn.f32x2 %0, %1, %2;" : "=l"(d) : "l"(a), "l"(b));
    return d;
}
__device__ __forceinline__ ull pack2(float lo, float hi) {
    ull d;
    asm("mov.b64 %0, {%1, %2};" : "=l"(d) : "f"(lo), "f"(hi));
    return d;
}
__device__ __forceinline__ float2 unpack2(ull v) {
    float2 r;
    asm("mov.b64 {%0, %1}, %2;" : "=f"(r.x), "=f"(r.y) : "l"(v));
    return r;
}

// ---------------------------------------------------------------------------
// Kernel 1: fused QKV 1x1-conv GEMM, f32x2 FMA, double-buffered smem +
// register prefetch.  Computes out[n][m] = sum_c W[m,c]*x[c,n] + bias[m]
// stored CHANNEL-LAST ([n][m], m fast).  M=128, N=16384, Kdim=128.
// blockIdx.y selects projection. BM=BN=128, BK=16, 256 thr, 8x8 per thread.
// ---------------------------------------------------------------------------
__global__ __launch_bounds__(256) void qkv_gemm(
    const float* __restrict__ x,
    const float* __restrict__ wq, const float* __restrict__ bq,
    const float* __restrict__ wk, const float* __restrict__ bk,
    const float* __restrict__ wv, const float* __restrict__ bv)
{
    __shared__ ull   Ws2[2][16][132];   // [buf][kk][m] duplicated (w,w) pairs
    __shared__ float Bs[2][16][128];    // [buf][kk][n]

    const float* W; const float* bias; float* out;
    if (blockIdx.y == 0)      { W = wq; bias = bq; out = g_q; }
    else if (blockIdx.y == 1) { W = wk; bias = bk; out = g_k; }
    else                      { W = wv; bias = bv; out = g_v; }

    const int tid = threadIdx.x;
    const int tx = tid & 15, ty = tid >> 4;
    const int n0 = blockIdx.x * 128;
    const int b  = n0 >> 12;
    const int hw0 = n0 & 4095;
    const float* xb = x + b * CHW + hw0;

    // stage tile 0 into buf 0
    {
        float wst, xst;
#pragma unroll
        for (int k = 0; k < 8; k++) {
            int t = tid + k * 256;
            wst = W[(t >> 4) * 128 + (t & 15)];
            xst = xb[(t >> 7) * HW + (t & 127)];
            Ws2[0][t & 15][t >> 4] = pack2(wst, wst);
            Bs[0][t >> 7][t & 127] = xst;
        }
    }
    __syncthreads();

    ull acc2[8][4];
#pragma unroll
    for (int i = 0; i < 8; i++)
#pragma unroll
        for (int j = 0; j < 4; j++) acc2[i][j] = 0ull;

#pragma unroll 1
    for (int it = 0; it < 8; it++) {
        const int cur = it & 1;
        // prefetch next tile into the other buffer (no one reads it: last
        // read finished at the sync closing iteration it-1)
        if (it < 7) {
            const int c1 = (it + 1) * 16;
            float wst[8], xst[8];
#pragma unroll
            for (int k = 0; k < 8; k++) {
                int t = tid + k * 256;
                wst[k] = W[(t >> 4) * 128 + c1 + (t & 15)];
                xst[k] = xb[(c1 + (t >> 7)) * HW + (t & 127)];
            }
#pragma unroll
            for (int k = 0; k < 8; k++) {
                int t = tid + k * 256;
                Ws2[cur ^ 1][t & 15][t >> 4] = pack2(wst[k], wst[k]);
                Bs[cur ^ 1][t >> 7][t & 127] = xst[k];
            }
        }

#pragma unroll
        for (int kk = 0; kk < 16; kk++) {
            ull a2[8];
            {
                ulonglong2 a01 = *(const ulonglong2*)&Ws2[cur][kk][ty * 4];
                ulonglong2 a23 = *(const ulonglong2*)&Ws2[cur][kk][ty * 4 + 2];
                ulonglong2 a45 = *(const ulonglong2*)&Ws2[cur][kk][64 + ty * 4];
                ulonglong2 a67 = *(const ulonglong2*)&Ws2[cur][kk][64 + ty * 4 + 2];
                a2[0] = a01.x; a2[1] = a01.y; a2[2] = a23.x; a2[3] = a23.y;
                a2[4] = a45.x; a2[5] = a45.y; a2[6] = a67.x; a2[7] = a67.y;
            }
            ulonglong2 bA = *(const ulonglong2*)&Bs[cur][kk][tx * 4];
            ulonglong2 bB = *(const ulonglong2*)&Bs[cur][kk][64 + tx * 4];
#pragma unroll
            for (int i = 0; i < 8; i++) {
                acc2[i][0] = fma2(a2[i], bA.x, acc2[i][0]);
                acc2[i][1] = fma2(a2[i], bA.y, acc2[i][1]);
                acc2[i][2] = fma2(a2[i], bB.x, acc2[i][2]);
                acc2[i][3] = fma2(a2[i], bB.y, acc2[i][3]);
            }
        }
        __syncthreads();
    }

    // transpose in registers, store channel-last: out[(n0+nl)*128 + m]
    float vo[8][8];   // [n-idx][m-idx]
#pragma unroll
    for (int i = 0; i < 8; i++)
#pragma unroll
        for (int jp = 0; jp < 4; jp++) {
            float2 f = unpack2(acc2[i][jp]);
            vo[jp * 2][i]     = f.x;
            vo[jp * 2 + 1][i] = f.y;
        }
    float4 bA4 = *(const float4*)&bias[ty * 4];
    float4 bB4 = *(const float4*)&bias[64 + ty * 4];
    float* outp = out + (size_t)n0 * 128;
#pragma unroll
    for (int jn = 0; jn < 8; jn++) {
        int nl = (jn < 4) ? (tx * 4 + jn) : (64 + tx * 4 + (jn - 4));
        float4 lo = make_float4(vo[jn][0] + bA4.x, vo[jn][1] + bA4.y,
                                vo[jn][2] + bA4.z, vo[jn][3] + bA4.w);
        float4 hi = make_float4(vo[jn][4] + bB4.x, vo[jn][5] + bB4.y,
                                vo[jn][6] + bB4.z, vo[jn][7] + bB4.w);
        *(float4*)(outp + (size_t)nl * 128 + ty * 4)      = lo;
        *(float4*)(outp + (size_t)nl * 128 + 64 + ty * 4) = hi;
    }
}

// ---------------------------------------------------------------------------
// Kernel 2: local attention, 2 adjacent pixels per thread, single-pass
// softmax without max subtraction (logits bounded << 88).
//
// Block = 16x32 pixel tile for one (b, head); 256 threads (16x16); thread
// (tx,ty) owns pixels (h0+ty, w0+2tx) and (h0+ty, w0+2tx+1).
//
// smem: interleaved K/V pair-blocks (conflict-free, proven R2):
//   word offset = r*1292 + (c>>1)*68 + (c&1)*16 (+32 for V) + d
// Halo 22 rows x 38 cols x 16 d -> 111 KB -> 2 blocks/SM (16 warps).
// Fill is float4-vectorized thanks to channel-last g_k/g_v.
// ---------------------------------------------------------------------------
#define RSTRIDE 1292             // 19 * 68
#define HROWS 22
#define SM_WORDS (HROWS * RSTRIDE) // 28424 words = 113696 B

__global__ __launch_bounds__(256, 2) void attn_kernel(
    const float* __restrict__ bk, const float* __restrict__ bv,
    const float* __restrict__ pos_h, const float* __restrict__ pos_w,
    float* __restrict__ outp)
{
    extern __shared__ float sm[];
    __shared__ float spos[16];   // [0..6]=pos_h row, [7..13]=pos_w row

    const int tr = blockIdx.x >> 1, tc = blockIdx.x & 1;
    const int h0 = tr * 16, w0 = tc * 32;
    const int nh = blockIdx.y, b = blockIdx.z;
    const int tx = threadIdx.x;   // 0..15
    const int ty = threadIdx.y;   // 0..15
    const int tid = ty * 16 + tx;
    const int cbase = nh * DHh;

    const float* kb = g_k + (size_t)b * CHW + cbase;
    const float* vb = g_v + (size_t)b * CHW + cbase;

    if (tid < 7)        spos[tid] = pos_h[nh * 7 + tid];
    else if (tid < 14)  spos[tid] = pos_w[nh * 7 + tid - 7];

    // ---- fill halo: 22 x 38 sites x 4 quads (float4), K+V per iter ----
    for (int idx = tid; idx < HROWS * 38 * 4; idx += 256) {
        int quad = idx & 3;
        int site = idx >> 2;
        int r = site / 38, c = site - r * 38;
        int gh = h0 - PADk + r, gw = w0 - PADk + c;
        float4 kq, vq;
        if ((unsigned)gh < (unsigned)Hh && (unsigned)gw < (unsigned)Ww) {
            size_t g = (size_t)(gh * Ww + gw) * Cc + quad * 4;
            kq = *(const float4*)(kb + g);
            vq = *(const float4*)(vb + g);
        } else {
            kq = *(const float4*)(bk + cbase + quad * 4);
            vq = *(const float4*)(bv + cbase + quad * 4);
        }
        int off = r * RSTRIDE + (c >> 1) * 68 + (c & 1) * 16 + quad * 4;
        *(float4*)(sm + off)      = kq;
        *(float4*)(sm + off + 32) = vq;
    }
    __syncthreads();

    // ---- load q for both pixels (channel-last: contiguous 16 floats) ----
    const int h = h0 + ty, w = w0 + 2 * tx;
    const float* qp = g_q + (size_t)b * CHW + (size_t)(h * Ww + w) * Cc + cbase;
    ull q0p[8], q1p[8];
#pragma unroll
    for (int t = 0; t < 4; t++) {
        float4 f0 = *(const float4*)(qp + t * 4);        // pixel0 d 4t..4t+3
        float4 f1 = *(const float4*)(qp + Cc + t * 4);   // pixel1
        q0p[2 * t]     = pack2(f0.x, f0.y);
        q0p[2 * t + 1] = pack2(f0.z, f0.w);
        q1p[2 * t]     = pack2(f1.x, f1.y);
        q1p[2 * t + 1] = pack2(f1.z, f1.w);
    }

    ull acc0[8], acc1[8];
#pragma unroll
    for (int t = 0; t < 8; t++) { acc0[t] = 0ull; acc1[t] = 0ull; }
    float sum0 = 0.f, sum1 = 0.f;

#pragma unroll 1
    for (int i = 0; i < 7; i++) {
        const float* rowp = sm + (ty + i) * RSTRIDE;
        const float phi = spos[i];
#pragma unroll
        for (int c = 0; c < 8; c++) {
            const float* p = rowp + (tx + (c >> 1)) * 68 + (c & 1) * 16;
            ulonglong2 kA = ((const ulonglong2*)p)[0];
            ulonglong2 kB = ((const ulonglong2*)p)[1];
            ulonglong2 kC = ((const ulonglong2*)p)[2];
            ulonglong2 kD = ((const ulonglong2*)p)[3];

            float w0e = 0.f, w1e = 0.f;
            if (c < 7) {   // pixel0 neighbor j = c
                ull sA = fma2(q0p[0], kA.x, 0ull);
                ull sB = fma2(q0p[1], kA.y, 0ull);
                sA = fma2(q0p[2], kB.x, sA);
                sB = fma2(q0p[3], kB.y, sB);
                sA = fma2(q0p[4], kC.x, sA);
                sB = fma2(q0p[5], kC.y, sB);
                sA = fma2(q0p[6], kD.x, sA);
                sB = fma2(q0p[7], kD.y, sB);
                float2 f = unpack2(add2(sA, sB));
                w0e = __expf(f.x + f.y + phi + spos[7 + c]);
                sum0 += w0e;
            }
            if (c >= 1) {  // pixel1 neighbor j = c-1
                ull sA = fma2(q1p[0], kA.x, 0ull);
                ull sB = fma2(q1p[1], kA.y, 0ull);
                sA = fma2(q1p[2], kB.x, sA);
                sB = fma2(q1p[3], kB.y, sB);
                sA = fma2(q1p[4], kC.x, sA);
                sB = fma2(q1p[5], kC.y, sB);
                sA = fma2(q1p[6], kD.x, sA);
                sB = fma2(q1p[7], kD.y, sB);
                float2 f = unpack2(add2(sA, sB));
                w1e = __expf(f.x + f.y + phi + spos[7 + c - 1]);
                sum1 += w1e;
            }

            const float* pv = p + 32;
            ulonglong2 vA = ((const ulonglong2*)pv)[0];
            ulonglong2 vB = ((const ulonglong2*)pv)[1];
            ulonglong2 vC = ((const ulonglong2*)pv)[2];
            ulonglong2 vD = ((const ulonglong2*)pv)[3];

            if (c < 7) {
                ull wp = pack2(w0e, w0e);
                acc0[0] = fma2(wp, vA.x, acc0[0]);
                acc0[1] = fma2(wp, vA.y, acc0[1]);
                acc0[2] = fma2(wp, vB.x, acc0[2]);
                acc0[3] = fma2(wp, vB.y, acc0[3]);
                acc0[4] = fma2(wp, vC.x, acc0[4]);
                acc0[5] = fma2(wp, vC.y, acc0[5]);
                acc0[6] = fma2(wp, vD.x, acc0[6]);
                acc0[7] = fma2(wp, vD.y, acc0[7]);
            }
            if (c >= 1) {
                ull wp = pack2(w1e, w1e);
                acc1[0] = fma2(wp, vA.x, acc1[0]);
                acc1[1] = fma2(wp, vA.y, acc1[1]);
                acc1[2] = fma2(wp, vB.x, acc1[2]);
                acc1[3] = fma2(wp, vB.y, acc1[3]);
                acc1[4] = fma2(wp, vC.x, acc1[4]);
                acc1[5] = fma2(wp, vC.y, acc1[5]);
                acc1[6] = fma2(wp, vD.x, acc1[6]);
                acc1[7] = fma2(wp, vD.y, acc1[7]);
            }
        }
    }

    const float inv0 = __fdividef(1.f, sum0);
    const float inv1 = __fdividef(1.f, sum1);

    // output stays standard [b][c][h][w]
    float* op = outp + ((size_t)(b * Cc + cbase) * Hh + h) * Ww + w;
#pragma unroll
    for (int t = 0; t < 8; t++) {
        float2 a0 = unpack2(acc0[t]);   // pixel0, d = 2t, 2t+1
        float2 a1 = unpack2(acc1[t]);   // pixel1
        float2 olo = make_float2(a0.x * inv0, a1.x * inv1);  // d = 2t
        float2 ohi = make_float2(a0.y * inv0, a1.y * inv1);  // d = 2t+1
        *(float2*)(op + (2 * t) * HW)     = olo;
        *(float2*)(op + (2 * t + 1) * HW) = ohi;
    }
}

// ---------------------------------------------------------------------------
extern "C" void kernel_launch(void* const* d_in, const int* in_sizes, int n_in,
                              void* d_out, int out_size) {
    const float* x  = (const float*)d_in[0];
    const float* wq = (const float*)d_in[1];
    const float* bq = (const float*)d_in[2];
    const float* wk = (const float*)d_in[3];
    const float* bk = (const float*)d_in[4];
    const float* wv = (const float*)d_in[5];
    const float* bv = (const float*)d_in[6];
    const float* ph = (const float*)d_in[7];
    const float* pw = (const float*)d_in[8];
    float* out = (float*)d_out;

    const size_t smem_bytes = SM_WORDS * sizeof(float);  // 113696
    cudaFuncSetAttribute((const void*)attn_kernel,
                         cudaFuncAttributeMaxDynamicSharedMemorySize,
                         (int)smem_bytes);

    qkv_gemm<<<dim3(128, 3), 256>>>(x, wq, bq, wk, bk, wv, bv);
    attn_kernel<<<dim3(8, NHh, Bsz), dim3(16, 16), smem_bytes>>>(bk, bv, ph, pw, out);
}

// round 5
// speedup vs baseline: 1.1893x; 1.0751x over previous
#include <cuda_runtime.h>

#define Bsz 4
#define Cc  128
#define Hh  64
#define Ww  64
#define Kk  7
#define NHh 8
#define DHh 16
#define PADk 3
#define HW  (Hh*Ww)        // 4096
#define CHW (Cc*HW)        // 524288

typedef unsigned long long ull;

// scratch for projections, CHANNEL-LAST layout [b][hw][c] (c = head*16+d)
__device__ float g_q[Bsz*CHW];
__device__ float g_k[Bsz*CHW];
__device__ float g_v[Bsz*CHW];

// ---------------- packed f32x2 helpers (sm_103a) ----------------
__device__ __forceinline__ ull fma2(ull a, ull b, ull c) {
    ull d;
    asm("fma.rn.f32x2 %0, %1, %2, %3;" : "=l"(d) : "l"(a), "l"(b), "l"(c));
    return d;
}
__device__ __forceinline__ ull add2(ull a, ull b) {
    ull d;
    asm("add.rn.f32x2 %0, %1, %2;" : "=l"(d) : "l"(a), "l"(b));
    return d;
}
__device__ __forceinline__ ull pack2(float lo, float hi) {
    ull d;
    asm("mov.b64 %0, {%1, %2};" : "=l"(d) : "f"(lo), "f"(hi));
    return d;
}
__device__ __forceinline__ float2 unpack2(ull v) {
    float2 r;
    asm("mov.b64 {%0, %1}, %2;" : "=f"(r.x), "=f"(r.y) : "l"(v));
    return r;
}

// ---------------------------------------------------------------------------
// Kernel 1: fused QKV 1x1-conv GEMM, f32x2, double-buffered, channel-last
// COALESCED store.  tx indexes m (8 m's as 4 pairs), ty indexes n (8 n's).
// out[n][m] (m fast).  M=128, N=16384, Kdim=128, BK=16, 256 thr.
// ---------------------------------------------------------------------------
__global__ __launch_bounds__(256) void qkv_gemm(
    const float* __restrict__ x,
    const float* __restrict__ wq, const float* __restrict__ bq,
    const float* __restrict__ wk, const float* __restrict__ bk,
    const float* __restrict__ wv, const float* __restrict__ bv)
{
    __shared__ float Ws[2][16][132];   // [buf][kk][m] plain floats
    __shared__ ull   Xs2[2][16][132];  // [buf][kk][n] duplicated (x,x) pairs

    const float* W; const float* bias; float* out;
    if (blockIdx.y == 0)      { W = wq; bias = bq; out = g_q; }
    else if (blockIdx.y == 1) { W = wk; bias = bk; out = g_k; }
    else                      { W = wv; bias = bv; out = g_v; }

    const int tid = threadIdx.x;
    const int tx = tid & 15, ty = tid >> 4;
    const int n0 = blockIdx.x * 128;
    const int b  = n0 >> 12;
    const int hw0 = n0 & 4095;
    const float* xb = x + b * CHW + hw0;

    // stage tile 0
#pragma unroll
    for (int k = 0; k < 8; k++) {
        int t = tid + k * 256;
        Ws[0][t & 15][t >> 4] = W[(t >> 4) * 128 + (t & 15)];
        float xv = xb[(t >> 7) * HW + (t & 127)];
        Xs2[0][t >> 7][t & 127] = pack2(xv, xv);
    }
    __syncthreads();

    ull acc2[8][4];   // [n-idx][m-pair]
#pragma unroll
    for (int i = 0; i < 8; i++)
#pragma unroll
        for (int j = 0; j < 4; j++) acc2[i][j] = 0ull;

#pragma unroll 1
    for (int it = 0; it < 8; it++) {
        const int cur = it & 1;
        if (it < 7) {
            const int c1 = (it + 1) * 16;
            float wst[8], xst[8];
#pragma unroll
            for (int k = 0; k < 8; k++) {
                int t = tid + k * 256;
                wst[k] = W[(t >> 4) * 128 + c1 + (t & 15)];
                xst[k] = xb[(c1 + (t >> 7)) * HW + (t & 127)];
            }
#pragma unroll
            for (int k = 0; k < 8; k++) {
                int t = tid + k * 256;
                Ws[cur ^ 1][t & 15][t >> 4] = wst[k];
                Xs2[cur ^ 1][t >> 7][t & 127] = pack2(xst[k], xst[k]);
            }
        }

#pragma unroll
        for (int kk = 0; kk < 16; kk++) {
            ull wp[4];
            {
                ulonglong2 w01 = *(const ulonglong2*)&Ws[cur][kk][tx * 4];
                ulonglong2 w23 = *(const ulonglong2*)&Ws[cur][kk][64 + tx * 4];
                wp[0] = w01.x; wp[1] = w01.y; wp[2] = w23.x; wp[3] = w23.y;
            }
            ull xd[8];
            {
                ulonglong2 xa = *(const ulonglong2*)&Xs2[cur][kk][ty * 4];
                ulonglong2 xbp = *(const ulonglong2*)&Xs2[cur][kk][ty * 4 + 2];
                ulonglong2 xc = *(const ulonglong2*)&Xs2[cur][kk][64 + ty * 4];
                ulonglong2 xdp = *(const ulonglong2*)&Xs2[cur][kk][64 + ty * 4 + 2];
                xd[0] = xa.x;  xd[1] = xa.y;  xd[2] = xbp.x; xd[3] = xbp.y;
                xd[4] = xc.x;  xd[5] = xc.y;  xd[6] = xdp.x; xd[7] = xdp.y;
            }
#pragma unroll
            for (int jn = 0; jn < 8; jn++) {
                acc2[jn][0] = fma2(wp[0], xd[jn], acc2[jn][0]);
                acc2[jn][1] = fma2(wp[1], xd[jn], acc2[jn][1]);
                acc2[jn][2] = fma2(wp[2], xd[jn], acc2[jn][2]);
                acc2[jn][3] = fma2(wp[3], xd[jn], acc2[jn][3]);
            }
        }
        __syncthreads();
    }

    // coalesced channel-last store: warp writes 256B contiguous per n-row
    float4 bA4 = *(const float4*)&bias[tx * 4];
    float4 bB4 = *(const float4*)&bias[64 + tx * 4];
    float* outp = out + (size_t)n0 * 128;
#pragma unroll
    for (int jn = 0; jn < 8; jn++) {
        int nl = (jn < 4) ? (ty * 4 + jn) : (64 + ty * 4 + (jn - 4));
        float2 f0 = unpack2(acc2[jn][0]);
        float2 f1 = unpack2(acc2[jn][1]);
        float2 f2 = unpack2(acc2[jn][2]);
        float2 f3 = unpack2(acc2[jn][3]);
        float4 lo = make_float4(f0.x + bA4.x, f0.y + bA4.y, f1.x + bA4.z, f1.y + bA4.w);
        float4 hi = make_float4(f2.x + bB4.x, f2.y + bB4.y, f3.x + bB4.z, f3.y + bB4.w);
        *(float4*)(outp + (size_t)nl * 128 + tx * 4)      = lo;
        *(float4*)(outp + (size_t)nl * 128 + 64 + tx * 4) = hi;
    }
}

// ---------------------------------------------------------------------------
// Kernel 2: local attention, split-d warp layout.
//
// Block = 8x32 pixel tile for one (b, head); 256 threads = 8 warps; warp =
// one pixel row. Lane = (lx, dh): lx = px-pair (2 adjacent pixels), dh =
// d-half (lane>=16 handles d8..15 of the SAME pixels). Partial 8-d dots are
// combined across the lane pair with one shfl.xor(16) per logit.
// Single-pass softmax without max subtraction (logits bounded << 88).
//
// smem: interleaved K/V pair-blocks (conflict-free):
//   word offset = r*1292 + (c>>1)*68 + (c&1)*16 (+32 for V) + d
// Halo 14 x 38 x 16 -> 72352 B -> 3 blocks/SM = 24 warps.
// ---------------------------------------------------------------------------
#define RSTRIDE 1292             // 19 * 68
#define HROWS 14
#define SM_WORDS (HROWS * RSTRIDE) // 18088 words = 72352 B

__global__ __launch_bounds__(256, 3) void attn_kernel(
    const float* __restrict__ bk, const float* __restrict__ bv,
    const float* __restrict__ pos_h, const float* __restrict__ pos_w,
    float* __restrict__ outp)
{
    extern __shared__ float sm[];
    __shared__ float spos[16];   // [0..6]=pos_h row, [7..13]=pos_w row

    const int tr = blockIdx.x >> 1, tc = blockIdx.x & 1;
    const int h0 = tr * 8, w0 = tc * 32;
    const int nh = blockIdx.y, b = blockIdx.z;
    const int tid = threadIdx.x;
    const int wid  = tid >> 5;      // warp = pixel row 0..7
    const int lane = tid & 31;
    const int lx   = lane & 15;     // px-pair index
    const int dh   = lane >> 4;     // d-half
    const int dbase = dh * 8;
    const int cbase = nh * DHh;

    const float* kb = g_k + (size_t)b * CHW + cbase;
    const float* vb = g_v + (size_t)b * CHW + cbase;

    if (tid < 7)        spos[tid] = pos_h[nh * 7 + tid];
    else if (tid < 14)  spos[tid] = pos_w[nh * 7 + tid - 7];

    // ---- fill halo: 14 x 38 sites x 4 quads (float4), K+V per iter ----
    for (int idx = tid; idx < HROWS * 38 * 4; idx += 256) {
        int quad = idx & 3;
        int site = idx >> 2;
        int r = site / 38, c = site - r * 38;
        int gh = h0 - PADk + r, gw = w0 - PADk + c;
        float4 kq, vq;
        if ((unsigned)gh < (unsigned)Hh && (unsigned)gw < (unsigned)Ww) {
            size_t g = (size_t)(gh * Ww + gw) * Cc + quad * 4;
            kq = *(const float4*)(kb + g);
            vq = *(const float4*)(vb + g);
        } else {
            kq = *(const float4*)(bk + cbase + quad * 4);
            vq = *(const float4*)(bv + cbase + quad * 4);
        }
        int off = r * RSTRIDE + (c >> 1) * 68 + (c & 1) * 16 + quad * 4;
        *(float4*)(sm + off)      = kq;
        *(float4*)(sm + off + 32) = vq;
    }
    __syncthreads();

    // ---- q for both pixels, this lane's d-half (4 packed pairs each) ----
    const int h = h0 + wid, w = w0 + 2 * lx;
    const float* qp = g_q + (size_t)b * CHW + (size_t)(h * Ww + w) * Cc + cbase + dbase;
    ull q0p[4], q1p[4];
    {
        ulonglong2 a = *(const ulonglong2*)qp;
        ulonglong2 bq2 = *(const ulonglong2*)(qp + 4);
        q0p[0] = a.x; q0p[1] = a.y; q0p[2] = bq2.x; q0p[3] = bq2.y;
        ulonglong2 c2 = *(const ulonglong2*)(qp + Cc);
        ulonglong2 d2 = *(const ulonglong2*)(qp + Cc + 4);
        q1p[0] = c2.x; q1p[1] = c2.y; q1p[2] = d2.x; q1p[3] = d2.y;
    }

    ull acc0[4], acc1[4];
#pragma unroll
    for (int t = 0; t < 4; t++) { acc0[t] = 0ull; acc1[t] = 0ull; }
    float sum0 = 0.f, sum1 = 0.f;

#pragma unroll 1
    for (int i = 0; i < 7; i++) {
        const float* rowp = sm + (wid + i) * RSTRIDE + dbase;
        const float phi = spos[i];
#pragma unroll
        for (int c = 0; c < 8; c++) {
            const float* p = rowp + (lx + (c >> 1)) * 68 + (c & 1) * 16;
            ulonglong2 kA = ((const ulonglong2*)p)[0];
            ulonglong2 kB = ((const ulonglong2*)p)[1];

            // partial 8-d dots for both pixels
            ull sA = fma2(q0p[0], kA.x, 0ull);
            ull sB = fma2(q0p[1], kA.y, 0ull);
            sA = fma2(q0p[2], kB.x, sA);
            sB = fma2(q0p[3], kB.y, sB);
            float2 f0 = unpack2(add2(sA, sB));
            float part0 = f0.x + f0.y;

            ull tA = fma2(q1p[0], kA.x, 0ull);
            ull tB = fma2(q1p[1], kA.y, 0ull);
            tA = fma2(q1p[2], kB.x, tA);
            tB = fma2(q1p[3], kB.y, tB);
            float2 f1 = unpack2(add2(tA, tB));
            float part1 = f1.x + f1.y;

            // combine d-halves across the lane pair
            float full0 = part0 + __shfl_xor_sync(0xffffffffu, part0, 16);
            float full1 = part1 + __shfl_xor_sync(0xffffffffu, part1, 16);

            float w0e = 0.f, w1e = 0.f;
            if (c < 7) {            // pixel0 neighbor j = c
                w0e = __expf(full0 + phi + spos[7 + c]);
                sum0 += w0e;
            }
            if (c >= 1) {           // pixel1 neighbor j = c-1
                w1e = __expf(full1 + phi + spos[6 + c]);
                sum1 += w1e;
            }

            const float* pv = p + 32;
            ulonglong2 vA = ((const ulonglong2*)pv)[0];
            ulonglong2 vB = ((const ulonglong2*)pv)[1];

            if (c < 7) {
                ull wp = pack2(w0e, w0e);
                acc0[0] = fma2(wp, vA.x, acc0[0]);
                acc0[1] = fma2(wp, vA.y, acc0[1]);
                acc0[2] = fma2(wp, vB.x, acc0[2]);
                acc0[3] = fma2(wp, vB.y, acc0[3]);
            }
            if (c >= 1) {
                ull wp = pack2(w1e, w1e);
                acc1[0] = fma2(wp, vA.x, acc1[0]);
                acc1[1] = fma2(wp, vA.y, acc1[1]);
                acc1[2] = fma2(wp, vB.x, acc1[2]);
                acc1[3] = fma2(wp, vB.y, acc1[3]);
            }
        }
    }

    const float inv0 = __fdividef(1.f, sum0);
    const float inv1 = __fdividef(1.f, sum1);

    // output standard [b][c][h][w]; lane writes its own d-half
    float* op = outp + ((size_t)(b * Cc + cbase + dbase) * Hh + h) * Ww + w;
#pragma unroll
    for (int t = 0; t < 4; t++) {
        float2 a0 = unpack2(acc0[t]);   // pixel0, d = dbase+2t, +2t+1
        float2 a1 = unpack2(acc1[t]);   // pixel1
        float2 olo = make_float2(a0.x * inv0, a1.x * inv1);
        float2 ohi = make_float2(a0.y * inv0, a1.y * inv1);
        *(float2*)(op + (2 * t) * HW)     = olo;
        *(float2*)(op + (2 * t + 1) * HW) = ohi;
    }
}

// ---------------------------------------------------------------------------
extern "C" void kernel_launch(void* const* d_in, const int* in_sizes, int n_in,
                              void* d_out, int out_size) {
    const float* x  = (const float*)d_in[0];
    const float* wq = (const float*)d_in[1];
    const float* bq = (const float*)d_in[2];
    const float* wk = (const float*)d_in[3];
    const float* bk = (const float*)d_in[4];
    const float* wv = (const float*)d_in[5];
    const float* bv = (const float*)d_in[6];
    const float* ph = (const float*)d_in[7];
    const float* pw = (const float*)d_in[8];
    float* out = (float*)d_out;

    const size_t smem_bytes = SM_WORDS * sizeof(float);  // 72352
    cudaFuncSetAttribute((const void*)attn_kernel,
                         cudaFuncAttributeMaxDynamicSharedMemorySize,
                         (int)smem_bytes);

    qkv_gemm<<<dim3(128, 3), 256>>>(x, wq, bq, wk, bk, wv, bv);
    attn_kernel<<<dim3(16, NHh, Bsz), 256, smem_bytes>>>(bk, bv, ph, pw, out);
}

// round 6
// speedup vs baseline: 1.2242x; 1.0294x over previous
#include <cuda_runtime.h>

#define Bsz 4
#define Cc  128
#define Hh  64
#define Ww  64
#define Kk  7
#define NHh 8
#define DHh 16
#define PADk 3
#define HW  (Hh*Ww)        // 4096
#define CHW (Cc*HW)        // 524288

typedef unsigned long long ull;

// scratch for projections, CHANNEL-LAST layout [b][hw][c] (c = head*16+d)
__device__ float g_q[Bsz*CHW];
__device__ float g_k[Bsz*CHW];
__device__ float g_v[Bsz*CHW];

// ---------------- packed f32x2 helpers (sm_103a) ----------------
__device__ __forceinline__ ull fma2(ull a, ull b, ull c) {
    ull d;
    asm("fma.rn.f32x2 %0, %1, %2, %3;" : "=l"(d) : "l"(a), "l"(b), "l"(c));
    return d;
}
__device__ __forceinline__ ull add2(ull a, ull b) {
    ull d;
    asm("add.rn.f32x2 %0, %1, %2;" : "=l"(d) : "l"(a), "l"(b));
    return d;
}
__device__ __forceinline__ ull pack2(float lo, float hi) {
    ull d;
    asm("mov.b64 %0, {%1, %2};" : "=l"(d) : "f"(lo), "f"(hi));
    return d;
}
__device__ __forceinline__ float2 unpack2(ull v) {
    float2 r;
    asm("mov.b64 {%0, %1}, %2;" : "=f"(r.x), "=f"(r.y) : "l"(v));
    return r;
}

// ---------------------------------------------------------------------------
// Kernel 1 (R5, proven 32.7us): fused QKV GEMM, f32x2, double-buffered,
// channel-last coalesced store.  tx->m (4 pairs), ty->n (8 n's).
// ---------------------------------------------------------------------------
__global__ __launch_bounds__(256) void qkv_gemm(
    const float* __restrict__ x,
    const float* __restrict__ wq, const float* __restrict__ bq,
    const float* __restrict__ wk, const float* __restrict__ bk,
    const float* __restrict__ wv, const float* __restrict__ bv)
{
    __shared__ float Ws[2][16][132];   // [buf][kk][m] plain floats
    __shared__ ull   Xs2[2][16][132];  // [buf][kk][n] duplicated (x,x) pairs

    const float* W; const float* bias; float* out;
    if (blockIdx.y == 0)      { W = wq; bias = bq; out = g_q; }
    else if (blockIdx.y == 1) { W = wk; bias = bk; out = g_k; }
    else                      { W = wv; bias = bv; out = g_v; }

    const int tid = threadIdx.x;
    const int tx = tid & 15, ty = tid >> 4;
    const int n0 = blockIdx.x * 128;
    const int b  = n0 >> 12;
    const int hw0 = n0 & 4095;
    const float* xb = x + b * CHW + hw0;

#pragma unroll
    for (int k = 0; k < 8; k++) {
        int t = tid + k * 256;
        Ws[0][t & 15][t >> 4] = W[(t >> 4) * 128 + (t & 15)];
        float xv = xb[(t >> 7) * HW + (t & 127)];
        Xs2[0][t >> 7][t & 127] = pack2(xv, xv);
    }
    __syncthreads();

    ull acc2[8][4];   // [n-idx][m-pair]
#pragma unroll
    for (int i = 0; i < 8; i++)
#pragma unroll
        for (int j = 0; j < 4; j++) acc2[i][j] = 0ull;

#pragma unroll 1
    for (int it = 0; it < 8; it++) {
        const int cur = it & 1;
        if (it < 7) {
            const int c1 = (it + 1) * 16;
            float wst[8], xst[8];
#pragma unroll
            for (int k = 0; k < 8; k++) {
                int t = tid + k * 256;
                wst[k] = W[(t >> 4) * 128 + c1 + (t & 15)];
                xst[k] = xb[(c1 + (t >> 7)) * HW + (t & 127)];
            }
#pragma unroll
            for (int k = 0; k < 8; k++) {
                int t = tid + k * 256;
                Ws[cur ^ 1][t & 15][t >> 4] = wst[k];
                Xs2[cur ^ 1][t >> 7][t & 127] = pack2(xst[k], xst[k]);
            }
        }

#pragma unroll
        for (int kk = 0; kk < 16; kk++) {
            ull wp[4];
            {
                ulonglong2 w01 = *(const ulonglong2*)&Ws[cur][kk][tx * 4];
                ulonglong2 w23 = *(const ulonglong2*)&Ws[cur][kk][64 + tx * 4];
                wp[0] = w01.x; wp[1] = w01.y; wp[2] = w23.x; wp[3] = w23.y;
            }
            ull xd[8];
            {
                ulonglong2 xa = *(const ulonglong2*)&Xs2[cur][kk][ty * 4];
                ulonglong2 xbp = *(const ulonglong2*)&Xs2[cur][kk][ty * 4 + 2];
                ulonglong2 xc = *(const ulonglong2*)&Xs2[cur][kk][64 + ty * 4];
                ulonglong2 xdp = *(const ulonglong2*)&Xs2[cur][kk][64 + ty * 4 + 2];
                xd[0] = xa.x;  xd[1] = xa.y;  xd[2] = xbp.x; xd[3] = xbp.y;
                xd[4] = xc.x;  xd[5] = xc.y;  xd[6] = xdp.x; xd[7] = xdp.y;
            }
#pragma unroll
            for (int jn = 0; jn < 8; jn++) {
                acc2[jn][0] = fma2(wp[0], xd[jn], acc2[jn][0]);
                acc2[jn][1] = fma2(wp[1], xd[jn], acc2[jn][1]);
                acc2[jn][2] = fma2(wp[2], xd[jn], acc2[jn][2]);
                acc2[jn][3] = fma2(wp[3], xd[jn], acc2[jn][3]);
            }
        }
        __syncthreads();
    }

    float4 bA4 = *(const float4*)&bias[tx * 4];
    float4 bB4 = *(const float4*)&bias[64 + tx * 4];
    float* outp = out + (size_t)n0 * 128;
#pragma unroll
    for (int jn = 0; jn < 8; jn++) {
        int nl = (jn < 4) ? (ty * 4 + jn) : (64 + ty * 4 + (jn - 4));
        float2 f0 = unpack2(acc2[jn][0]);
        float2 f1 = unpack2(acc2[jn][1]);
        float2 f2 = unpack2(acc2[jn][2]);
        float2 f3 = unpack2(acc2[jn][3]);
        float4 lo = make_float4(f0.x + bA4.x, f0.y + bA4.y, f1.x + bA4.z, f1.y + bA4.w);
        float4 hi = make_float4(f2.x + bB4.x, f2.y + bB4.y, f3.x + bB4.z, f3.y + bB4.w);
        *(float4*)(outp + (size_t)nl * 128 + tx * 4)      = lo;
        *(float4*)(outp + (size_t)nl * 128 + 64 + tx * 4) = hi;
    }
}

// ---------------------------------------------------------------------------
// Kernel 2 (R4 structure, proven 32.6us) + tweaks: q-load hoisted above the
// barrier; positional bias factored out of the exp via a 49-entry
// ehw[i][j] = exp(ph_i + pw_j) table (softmax-invariant).
//
// Block = 16x32 pixel tile for one (b, head); 256 threads (16x16); thread
// (tx,ty) owns pixels (h0+ty, w0+2tx) and (h0+ty, w0+2tx+1).
// Single-pass softmax without max subtraction (logits bounded << 88).
//
// smem: interleaved K/V pair-blocks (conflict-free):
//   word offset = r*1292 + (c>>1)*68 + (c&1)*16 (+32 for V) + d
// Halo 22 x 38 x 16 -> 113696 B -> 2 blocks/SM.
// ---------------------------------------------------------------------------
#define RSTRIDE 1292             // 19 * 68
#define HROWS 22
#define SM_WORDS (HROWS * RSTRIDE) // 28424 words = 113696 B

__global__ __launch_bounds__(256, 2) void attn_kernel(
    const float* __restrict__ bk, const float* __restrict__ bv,
    const float* __restrict__ pos_h, const float* __restrict__ pos_w,
    float* __restrict__ outp)
{
    extern __shared__ float sm[];
    __shared__ float ehw[52];    // [i*7+j] = exp(ph[i] + pw[j])

    const int tr = blockIdx.x >> 1, tc = blockIdx.x & 1;
    const int h0 = tr * 16, w0 = tc * 32;
    const int nh = blockIdx.y, b = blockIdx.z;
    const int tx = threadIdx.x;   // 0..15
    const int ty = threadIdx.y;   // 0..15
    const int tid = ty * 16 + tx;
    const int cbase = nh * DHh;

    const float* kb = g_k + (size_t)b * CHW + cbase;
    const float* vb = g_v + (size_t)b * CHW + cbase;

    if (tid < 49)
        ehw[tid] = __expf(pos_h[nh * 7 + tid / 7] + pos_w[nh * 7 + tid % 7]);

    // ---- q loads issued BEFORE the barrier (overlap with halo fill) ----
    const int h = h0 + ty, w = w0 + 2 * tx;
    const float* qp = g_q + (size_t)b * CHW + (size_t)(h * Ww + w) * Cc + cbase;
    float4 qf0[4], qf1[4];
#pragma unroll
    for (int t = 0; t < 4; t++) {
        qf0[t] = *(const float4*)(qp + t * 4);        // pixel0 d 4t..4t+3
        qf1[t] = *(const float4*)(qp + Cc + t * 4);   // pixel1
    }

    // ---- fill halo: 22 x 38 sites x 4 quads (float4), K+V per iter ----
    for (int idx = tid; idx < HROWS * 38 * 4; idx += 256) {
        int quad = idx & 3;
        int site = idx >> 2;
        int r = site / 38, c = site - r * 38;
        int gh = h0 - PADk + r, gw = w0 - PADk + c;
        float4 kq, vq;
        if ((unsigned)gh < (unsigned)Hh && (unsigned)gw < (unsigned)Ww) {
            size_t g = (size_t)(gh * Ww + gw) * Cc + quad * 4;
            kq = *(const float4*)(kb + g);
            vq = *(const float4*)(vb + g);
        } else {
            kq = *(const float4*)(bk + cbase + quad * 4);
            vq = *(const float4*)(bv + cbase + quad * 4);
        }
        int off = r * RSTRIDE + (c >> 1) * 68 + (c & 1) * 16 + quad * 4;
        *(float4*)(sm + off)      = kq;
        *(float4*)(sm + off + 32) = vq;
    }
    __syncthreads();

    ull q0p[8], q1p[8];
#pragma unroll
    for (int t = 0; t < 4; t++) {
        q0p[2 * t]     = pack2(qf0[t].x, qf0[t].y);
        q0p[2 * t + 1] = pack2(qf0[t].z, qf0[t].w);
        q1p[2 * t]     = pack2(qf1[t].x, qf1[t].y);
        q1p[2 * t + 1] = pack2(qf1[t].z, qf1[t].w);
    }

    ull acc0[8], acc1[8];
#pragma unroll
    for (int t = 0; t < 8; t++) { acc0[t] = 0ull; acc1[t] = 0ull; }
    float sum0 = 0.f, sum1 = 0.f;

#pragma unroll 1
    for (int i = 0; i < 7; i++) {
        const float* rowp = sm + (ty + i) * RSTRIDE;
        const float* eh_row = ehw + i * 7;
#pragma unroll
        for (int c = 0; c < 8; c++) {
            const float* p = rowp + (tx + (c >> 1)) * 68 + (c & 1) * 16;
            ulonglong2 kA = ((const ulonglong2*)p)[0];
            ulonglong2 kB = ((const ulonglong2*)p)[1];
            ulonglong2 kC = ((const ulonglong2*)p)[2];
            ulonglong2 kD = ((const ulonglong2*)p)[3];

            float w0e = 0.f, w1e = 0.f;
            if (c < 7) {   // pixel0 neighbor j = c
                ull sA = fma2(q0p[0], kA.x, 0ull);
                ull sB = fma2(q0p[1], kA.y, 0ull);
                sA = fma2(q0p[2], kB.x, sA);
                sB = fma2(q0p[3], kB.y, sB);
                sA = fma2(q0p[4], kC.x, sA);
                sB = fma2(q0p[5], kC.y, sB);
                sA = fma2(q0p[6], kD.x, sA);
                sB = fma2(q0p[7], kD.y, sB);
                float2 f = unpack2(add2(sA, sB));
                w0e = __expf(f.x + f.y) * eh_row[c];
                sum0 += w0e;
            }
            if (c >= 1) {  // pixel1 neighbor j = c-1
                ull sA = fma2(q1p[0], kA.x, 0ull);
                ull sB = fma2(q1p[1], kA.y, 0ull);
                sA = fma2(q1p[2], kB.x, sA);
                sB = fma2(q1p[3], kB.y, sB);
                sA = fma2(q1p[4], kC.x, sA);
                sB = fma2(q1p[5], kC.y, sB);
                sA = fma2(q1p[6], kD.x, sA);
                sB = fma2(q1p[7], kD.y, sB);
                float2 f = unpack2(add2(sA, sB));
                w1e = __expf(f.x + f.y) * eh_row[c - 1];
                sum1 += w1e;
            }

            const float* pv = p + 32;
            ulonglong2 vA = ((const ulonglong2*)pv)[0];
            ulonglong2 vB = ((const ulonglong2*)pv)[1];
            ulonglong2 vC = ((const ulonglong2*)pv)[2];
            ulonglong2 vD = ((const ulonglong2*)pv)[3];

            if (c < 7) {
                ull wp = pack2(w0e, w0e);
                acc0[0] = fma2(wp, vA.x, acc0[0]);
                acc0[1] = fma2(wp, vA.y, acc0[1]);
                acc0[2] = fma2(wp, vB.x, acc0[2]);
                acc0[3] = fma2(wp, vB.y, acc0[3]);
                acc0[4] = fma2(wp, vC.x, acc0[4]);
                acc0[5] = fma2(wp, vC.y, acc0[5]);
                acc0[6] = fma2(wp, vD.x, acc0[6]);
                acc0[7] = fma2(wp, vD.y, acc0[7]);
            }
            if (c >= 1) {
                ull wp = pack2(w1e, w1e);
                acc1[0] = fma2(wp, vA.x, acc1[0]);
                acc1[1] = fma2(wp, vA.y, acc1[1]);
                acc1[2] = fma2(wp, vB.x, acc1[2]);
                acc1[3] = fma2(wp, vB.y, acc1[3]);
                acc1[4] = fma2(wp, vC.x, acc1[4]);
                acc1[5] = fma2(wp, vC.y, acc1[5]);
                acc1[6] = fma2(wp, vD.x, acc1[6]);
                acc1[7] = fma2(wp, vD.y, acc1[7]);
            }
        }
    }

    const float inv0 = __fdividef(1.f, sum0);
    const float inv1 = __fdividef(1.f, sum1);

    // output standard [b][c][h][w]
    float* op = outp + ((size_t)(b * Cc + cbase) * Hh + h) * Ww + w;
#pragma unroll
    for (int t = 0; t < 8; t++) {
        float2 a0 = unpack2(acc0[t]);   // pixel0, d = 2t, 2t+1
        float2 a1 = unpack2(acc1[t]);   // pixel1
        float2 olo = make_float2(a0.x * inv0, a1.x * inv1);
        float2 ohi = make_float2(a0.y * inv0, a1.y * inv1);
        *(float2*)(op + (2 * t) * HW)     = olo;
        *(float2*)(op + (2 * t + 1) * HW) = ohi;
    }
}

// ---------------------------------------------------------------------------
extern "C" void kernel_launch(void* const* d_in, const int* in_sizes, int n_in,
                              void* d_out, int out_size) {
    const float* x  = (const float*)d_in[0];
    const float* wq = (const float*)d_in[1];
    const float* bq = (const float*)d_in[2];
    const float* wk = (const float*)d_in[3];
    const float* bk = (const float*)d_in[4];
    const float* wv = (const float*)d_in[5];
    const float* bv = (const float*)d_in[6];
    const float* ph = (const float*)d_in[7];
    const float* pw = (const float*)d_in[8];
    float* out = (float*)d_out;

    const size_t smem_bytes = SM_WORDS * sizeof(float);  // 113696
    cudaFuncSetAttribute((const void*)attn_kernel,
                         cudaFuncAttributeMaxDynamicSharedMemorySize,
                         (int)smem_bytes);

    qkv_gemm<<<dim3(128, 3), 256>>>(x, wq, bq, wk, bk, wv, bv);
    attn_kernel<<<dim3(8, NHh, Bsz), dim3(16, 16), smem_bytes>>>(bk, bv, ph, pw, out);
}

// round 8
// speedup vs baseline: 1.7548x; 1.4334x over previous
#include <cuda_runtime.h>
#include <cuda_bf16.h>
#include <cstdint>

#define Bsz 4
#define Cc  128
#define Hh  64
#define Ww  64
#define Kk  7
#define NHh 8
#define DHh 16
#define PADk 3
#define HW  (Hh*Ww)        // 4096
#define CHW (Cc*HW)        // 524288

typedef unsigned long long ull;

// scratch for projections, CHANNEL-LAST layout [b][hw][c]
__device__ float g_q[Bsz*CHW];
__device__ float g_k[Bsz*CHW];
__device__ float g_v[Bsz*CHW];

// ---------------- packed f32x2 helpers ----------------
__device__ __forceinline__ ull fma2(ull a, ull b, ull c) {
    ull d; asm("fma.rn.f32x2 %0, %1, %2, %3;" : "=l"(d) : "l"(a), "l"(b), "l"(c)); return d;
}
__device__ __forceinline__ ull add2(ull a, ull b) {
    ull d; asm("add.rn.f32x2 %0, %1, %2;" : "=l"(d) : "l"(a), "l"(b)); return d;
}
__device__ __forceinline__ ull pack2(float lo, float hi) {
    ull d; asm("mov.b64 %0, {%1, %2};" : "=l"(d) : "f"(lo), "f"(hi)); return d;
}
__device__ __forceinline__ float2 unpack2(ull v) {
    float2 r; asm("mov.b64 {%0, %1}, %2;" : "=f"(r.x), "=f"(r.y) : "l"(v)); return r;
}

// ---------------- HMMA helpers (sm_80+; no 'a' feature needed) ----------------
__device__ __forceinline__ uint32_t smem_u32(const void* p) {
    uint32_t a;
    asm("{ .reg .u64 t; cvta.to.shared.u64 t, %1; cvt.u32.u64 %0, t; }" : "=r"(a) : "l"(p));
    return a;
}
__device__ __forceinline__ void ldsm_x4(uint32_t& r0, uint32_t& r1, uint32_t& r2,
                                        uint32_t& r3, uint32_t addr) {
    asm volatile("ldmatrix.sync.aligned.m8n8.x4.shared.b16 {%0,%1,%2,%3}, [%4];"
                 : "=r"(r0), "=r"(r1), "=r"(r2), "=r"(r3) : "r"(addr));
}
__device__ __forceinline__ void mma_bf16(float* c, const uint32_t* a, const uint32_t* b) {
    asm volatile(
        "mma.sync.aligned.m16n8k16.row.col.f32.bf16.bf16.f32 "
        "{%0,%1,%2,%3}, {%4,%5,%6,%7}, {%8,%9}, {%0,%1,%2,%3};"
        : "+f"(c[0]), "+f"(c[1]), "+f"(c[2]), "+f"(c[3])
        : "r"(a[0]), "r"(a[1]), "r"(a[2]), "r"(a[3]), "r"(b[0]), "r"(b[1]));
}

// ---------------------------------------------------------------------------
// Kernel 1: fused QKV 1x1-conv GEMM via HMMA (bf16 hi/lo split, 3 terms).
// Grid = 128 blocks (one per 128 pixels, single wave). 256 thr = 8 warps in
// 4x2 (warp tile 32m x 64n). X split into smem once, reused for q/k/v.
// Output channel-last g_*[ (b*4096+hw)*128 + m ].
// ---------------------------------------------------------------------------
#define LDK 136                         // padded bf16 row length (272 B)
#define XHI_OFF 0
#define XLO_OFF (128 * LDK * 2)         // 34816
#define WHI_OFF (2 * 128 * LDK * 2)     // 69632
#define WLO_OFF (3 * 128 * LDK * 2)     // 104448
#define GEMM_SMEM (4 * 128 * LDK * 2)   // 139264 B

__global__ __launch_bounds__(256) void qkv_hmma(
    const float* __restrict__ x,
    const float* __restrict__ wq, const float* __restrict__ bq,
    const float* __restrict__ wk, const float* __restrict__ bk,
    const float* __restrict__ wv, const float* __restrict__ bv)
{
    extern __shared__ char smc[];
    unsigned short* Xhi = (unsigned short*)(smc + XHI_OFF);
    unsigned short* Xlo = (unsigned short*)(smc + XLO_OFF);
    unsigned short* Whi = (unsigned short*)(smc + WHI_OFF);
    unsigned short* Wlo = (unsigned short*)(smc + WLO_OFF);
    const uint32_t sb = smem_u32(smc);

    const int tid = threadIdx.x;
    const int warp = tid >> 5, lane = tid & 31;
    const int wy = warp >> 1, wx = warp & 1;   // m = wy*32, n = wx*64
    const int n0 = blockIdx.x * 128;
    const int b = n0 >> 12, hw0 = n0 & 4095;
    const float* xb = x + (size_t)b * CHW + hw0;

    // ---- X tile: fp32 -> bf16 hi/lo, transposed to [n][k] (once) ----
    for (int e = tid; e < 16384; e += 256) {
        int c = e >> 7, n = e & 127;
        float v = xb[c * HW + n];
        __nv_bfloat16 h = __float2bfloat16(v);
        __nv_bfloat16 l = __float2bfloat16(v - __bfloat162float(h));
        Xhi[n * LDK + c] = __bfloat16_as_ushort(h);
        Xlo[n * LDK + c] = __bfloat16_as_ushort(l);
    }

#pragma unroll 1
    for (int p = 0; p < 3; p++) {
        const float* Wp  = (p == 0) ? wq : (p == 1) ? wk : wv;
        const float* bp  = (p == 0) ? bq : (p == 1) ? bk : bv;
        float* og        = ((p == 0) ? g_q : (p == 1) ? g_k : g_v) + (size_t)n0 * 128;

        __syncthreads();   // X ready (p=0) / previous mma reads of W done
        // ---- W tile: [m][k] same orientation as gmem; vectorized split ----
        for (int e = tid * 4; e < 16384; e += 1024) {
            int m = e >> 7, c = e & 127;
            float4 v4 = *(const float4*)&Wp[m * 128 + c];
            ushort4 h4, l4;
            {
                __nv_bfloat16 h;
                h = __float2bfloat16(v4.x); h4.x = __bfloat16_as_ushort(h);
                l4.x = __bfloat16_as_ushort(__float2bfloat16(v4.x - __bfloat162float(h)));
                h = __float2bfloat16(v4.y); h4.y = __bfloat16_as_ushort(h);
                l4.y = __bfloat16_as_ushort(__float2bfloat16(v4.y - __bfloat162float(h)));
                h = __float2bfloat16(v4.z); h4.z = __bfloat16_as_ushort(h);
                l4.z = __bfloat16_as_ushort(__float2bfloat16(v4.z - __bfloat162float(h)));
                h = __float2bfloat16(v4.w); h4.w = __bfloat16_as_ushort(h);
                l4.w = __bfloat16_as_ushort(__float2bfloat16(v4.w - __bfloat162float(h)));
            }
            *(ushort4*)&Whi[m * LDK + c] = h4;
            *(ushort4*)&Wlo[m * LDK + c] = l4;
        }
        __syncthreads();

        // ---- MMA sweep ----
        float acc[2][8][4];
#pragma unroll
        for (int i = 0; i < 2; i++)
#pragma unroll
            for (int j = 0; j < 8; j++)
#pragma unroll
                for (int t = 0; t < 4; t++) acc[i][j][t] = 0.f;

#pragma unroll
        for (int k = 0; k < 8; k++) {
            const int kb = k * 16;
            uint32_t ahi[2][4], alo[2][4];
#pragma unroll
            for (int mf = 0; mf < 2; mf++) {
                int row = wy * 32 + mf * 16 + (lane & 15);
                int col = kb + ((lane >> 4) << 3);
                uint32_t off = (uint32_t)(row * LDK + col) * 2;
                ldsm_x4(ahi[mf][0], ahi[mf][1], ahi[mf][2], ahi[mf][3],
                        sb + WHI_OFF + off);
                ldsm_x4(alo[mf][0], alo[mf][1], alo[mf][2], alo[mf][3],
                        sb + WLO_OFF + off);
            }
            uint32_t bhi[8][2], blo[8][2];
#pragma unroll
            for (int nf4 = 0; nf4 < 4; nf4++) {
                int g = lane >> 3;
                int row = wx * 64 + nf4 * 16 + (lane & 7) + ((g & 2) << 2);
                int col = kb + ((g & 1) << 3);
                uint32_t off = (uint32_t)(row * LDK + col) * 2;
                uint32_t r0, r1, r2, r3;
                ldsm_x4(r0, r1, r2, r3, sb + XHI_OFF + off);
                bhi[nf4 * 2][0] = r0; bhi[nf4 * 2][1] = r1;
                bhi[nf4 * 2 + 1][0] = r2; bhi[nf4 * 2 + 1][1] = r3;
                ldsm_x4(r0, r1, r2, r3, sb + XLO_OFF + off);
                blo[nf4 * 2][0] = r0; blo[nf4 * 2][1] = r1;
                blo[nf4 * 2 + 1][0] = r2; blo[nf4 * 2 + 1][1] = r3;
            }
#pragma unroll
            for (int mf = 0; mf < 2; mf++)
#pragma unroll
                for (int nf = 0; nf < 8; nf++) {
                    mma_bf16(acc[mf][nf], ahi[mf], bhi[nf]);
                    mma_bf16(acc[mf][nf], ahi[mf], blo[nf]);
                    mma_bf16(acc[mf][nf], alo[mf], bhi[nf]);
                }
        }

        // ---- epilogue: channel-last store ----
#pragma unroll
        for (int mf = 0; mf < 2; mf++) {
            int r0 = wy * 32 + mf * 16 + (lane >> 2);
            int r1 = r0 + 8;
            float bi0 = bp[r0], bi1 = bp[r1];
#pragma unroll
            for (int nf = 0; nf < 8; nf++) {
                int c0 = wx * 64 + nf * 8 + (lane & 3) * 2;
                float* o0 = og + (size_t)c0 * 128;
                float* o1 = o0 + 128;
                o0[r0] = acc[mf][nf][0] + bi0;
                o1[r0] = acc[mf][nf][1] + bi0;
                o0[r1] = acc[mf][nf][2] + bi1;
                o1[r1] = acc[mf][nf][3] + bi1;
            }
        }
    }
}

// ---------------------------------------------------------------------------
// Kernel 2: local attention (R6, proven ~34us). 16x32 tile, 2 px/thread,
// single-pass softmax, interleaved K/V pair-block smem, ehw table.
// ---------------------------------------------------------------------------
#define RSTRIDE 1292             // 19 * 68
#define HROWS 22
#define SM_WORDS (HROWS * RSTRIDE) // 113696 B

__global__ __launch_bounds__(256, 2) void attn_kernel(
    const float* __restrict__ bk, const float* __restrict__ bv,
    const float* __restrict__ pos_h, const float* __restrict__ pos_w,
    float* __restrict__ outp)
{
    extern __shared__ float sm[];
    __shared__ float ehw[52];

    const int tr = blockIdx.x >> 1, tc = blockIdx.x & 1;
    const int h0 = tr * 16, w0 = tc * 32;
    const int nh = blockIdx.y, b = blockIdx.z;
    const int tx = threadIdx.x, ty = threadIdx.y;
    const int tid = ty * 16 + tx;
    const int cbase = nh * DHh;

    const float* kb = g_k + (size_t)b * CHW + cbase;
    const float* vb = g_v + (size_t)b * CHW + cbase;

    if (tid < 49)
        ehw[tid] = __expf(pos_h[nh * 7 + tid / 7] + pos_w[nh * 7 + tid % 7]);

    const int h = h0 + ty, w = w0 + 2 * tx;
    const float* qp = g_q + (size_t)b * CHW + (size_t)(h * Ww + w) * Cc + cbase;
    float4 qf0[4], qf1[4];
#pragma unroll
    for (int t = 0; t < 4; t++) {
        qf0[t] = *(const float4*)(qp + t * 4);
        qf1[t] = *(const float4*)(qp + Cc + t * 4);
    }

    for (int idx = tid; idx < HROWS * 38 * 4; idx += 256) {
        int quad = idx & 3;
        int site = idx >> 2;
        int r = site / 38, c = site - r * 38;
        int gh = h0 - PADk + r, gw = w0 - PADk + c;
        float4 kq, vq;
        if ((unsigned)gh < (unsigned)Hh && (unsigned)gw < (unsigned)Ww) {
            size_t g = (size_t)(gh * Ww + gw) * Cc + quad * 4;
            kq = *(const float4*)(kb + g);
            vq = *(const float4*)(vb + g);
        } else {
            kq = *(const float4*)(bk + cbase + quad * 4);
            vq = *(const float4*)(bv + cbase + quad * 4);
        }
        int off = r * RSTRIDE + (c >> 1) * 68 + (c & 1) * 16 + quad * 4;
        *(float4*)(sm + off)      = kq;
        *(float4*)(sm + off + 32) = vq;
    }
    __syncthreads();

    ull q0p[8], q1p[8];
#pragma unroll
    for (int t = 0; t < 4; t++) {
        q0p[2 * t]     = pack2(qf0[t].x, qf0[t].y);
        q0p[2 * t + 1] = pack2(qf0[t].z, qf0[t].w);
        q1p[2 * t]     = pack2(qf1[t].x, qf1[t].y);
        q1p[2 * t + 1] = pack2(qf1[t].z, qf1[t].w);
    }

    ull acc0[8], acc1[8];
#pragma unroll
    for (int t = 0; t < 8; t++) { acc0[t] = 0ull; acc1[t] = 0ull; }
    float sum0 = 0.f, sum1 = 0.f;

#pragma unroll 1
    for (int i = 0; i < 7; i++) {
        const float* rowp = sm + (ty + i) * RSTRIDE;
        const float* eh_row = ehw + i * 7;
#pragma unroll
        for (int c = 0; c < 8; c++) {
            const float* p = rowp + (tx + (c >> 1)) * 68 + (c & 1) * 16;
            ulonglong2 kA = ((const ulonglong2*)p)[0];
            ulonglong2 kB = ((const ulonglong2*)p)[1];
            ulonglong2 kC = ((const ulonglong2*)p)[2];
            ulonglong2 kD = ((const ulonglong2*)p)[3];

            float w0e = 0.f, w1e = 0.f;
            if (c < 7) {
                ull sA = fma2(q0p[0], kA.x, 0ull);
                ull sB = fma2(q0p[1], kA.y, 0ull);
                sA = fma2(q0p[2], kB.x, sA);
                sB = fma2(q0p[3], kB.y, sB);
                sA = fma2(q0p[4], kC.x, sA);
                sB = fma2(q0p[5], kC.y, sB);
                sA = fma2(q0p[6], kD.x, sA);
                sB = fma2(q0p[7], kD.y, sB);
                float2 f = unpack2(add2(sA, sB));
                w0e = __expf(f.x + f.y) * eh_row[c];
                sum0 += w0e;
            }
            if (c >= 1) {
                ull sA = fma2(q1p[0], kA.x, 0ull);
                ull sB = fma2(q1p[1], kA.y, 0ull);
                sA = fma2(q1p[2], kB.x, sA);
                sB = fma2(q1p[3], kB.y, sB);
                sA = fma2(q1p[4], kC.x, sA);
                sB = fma2(q1p[5], kC.y, sB);
                sA = fma2(q1p[6], kD.x, sA);
                sB = fma2(q1p[7], kD.y, sB);
                float2 f = unpack2(add2(sA, sB));
                w1e = __expf(f.x + f.y) * eh_row[c - 1];
                sum1 += w1e;
            }

            const float* pv = p + 32;
            ulonglong2 vA = ((const ulonglong2*)pv)[0];
            ulonglong2 vB = ((const ulonglong2*)pv)[1];
            ulonglong2 vC = ((const ulonglong2*)pv)[2];
            ulonglong2 vD = ((const ulonglong2*)pv)[3];

            if (c < 7) {
                ull wp = pack2(w0e, w0e);
                acc0[0] = fma2(wp, vA.x, acc0[0]);
                acc0[1] = fma2(wp, vA.y, acc0[1]);
                acc0[2] = fma2(wp, vB.x, acc0[2]);
                acc0[3] = fma2(wp, vB.y, acc0[3]);
                acc0[4] = fma2(wp, vC.x, acc0[4]);
                acc0[5] = fma2(wp, vC.y, acc0[5]);
                acc0[6] = fma2(wp, vD.x, acc0[6]);
                acc0[7] = fma2(wp, vD.y, acc0[7]);
            }
            if (c >= 1) {
                ull wp = pack2(w1e, w1e);
                acc1[0] = fma2(wp, vA.x, acc1[0]);
                acc1[1] = fma2(wp, vA.y, acc1[1]);
                acc1[2] = fma2(wp, vB.x, acc1[2]);
                acc1[3] = fma2(wp, vB.y, acc1[3]);
                acc1[4] = fma2(wp, vC.x, acc1[4]);
                acc1[5] = fma2(wp, vC.y, acc1[5]);
                acc1[6] = fma2(wp, vD.x, acc1[6]);
                acc1[7] = fma2(wp, vD.y, acc1[7]);
            }
        }
    }

    const float inv0 = __fdividef(1.f, sum0);
    const float inv1 = __fdividef(1.f, sum1);

    float* op = outp + ((size_t)(b * Cc + cbase) * Hh + h) * Ww + w;
#pragma unroll
    for (int t = 0; t < 8; t++) {
        float2 a0 = unpack2(acc0[t]);
        float2 a1 = unpack2(acc1[t]);
        float2 olo = make_float2(a0.x * inv0, a1.x * inv1);
        float2 ohi = make_float2(a0.y * inv0, a1.y * inv1);
        *(float2*)(op + (2 * t) * HW)     = olo;
        *(float2*)(op + (2 * t + 1) * HW) = ohi;
    }
}

// ---------------------------------------------------------------------------
extern "C" void kernel_launch(void* const* d_in, const int* in_sizes, int n_in,
                              void* d_out, int out_size) {
    const float* x  = (const float*)d_in[0];
    const float* wq = (const float*)d_in[1];
    const float* bq = (const float*)d_in[2];
    const float* wk = (const float*)d_in[3];
    const float* bk = (const float*)d_in[4];
    const float* wv = (const float*)d_in[5];
    const float* bv = (const float*)d_in[6];
    const float* ph = (const float*)d_in[7];
    const float* pw = (const float*)d_in[8];
    float* out = (float*)d_out;

    cudaFuncSetAttribute((const void*)qkv_hmma,
                         cudaFuncAttributeMaxDynamicSharedMemorySize, GEMM_SMEM);
    const size_t attn_smem = SM_WORDS * sizeof(float);
    cudaFuncSetAttribute((const void*)attn_kernel,
                         cudaFuncAttributeMaxDynamicSharedMemorySize, (int)attn_smem);

    qkv_hmma<<<128, 256, GEMM_SMEM>>>(x, wq, bq, wk, bk, wv, bv);
    attn_kernel<<<dim3(8, NHh, Bsz), dim3(16, 16), attn_smem>>>(bk, bv, ph, pw, out);
}